// round 13
// baseline (speedup 1.0000x reference)
#include <cuda_runtime.h>
#include <cuda_fp16.h>
#include <math.h>
#include <stdint.h>

#define NN 50000
#define EE 800000
#define RMS_EPS 1.1920928955078125e-07f

// ---------------- scratch (static __device__, no runtime alloc) -------------
__device__ float  g_xl[NN * 128];
__device__ float  g_h[NN * 128];        // post-norm1 hidden
__device__ float  g_H1[NN * 512];       // FFN intermediate (head reused as xr)
__device__ int2   g_pse[EE];            // (src, edge_id) in CSR order
__device__ int    g_rowptr[NN + 1];
__device__ int    g_cursor[NN];
__device__ int    g_deg[NN];
__device__ int    g_bsum[64];

// ============================ tf32 tensor-core GEMM =========================
__device__ __forceinline__ void mma_tf32(float c[4], const uint32_t a[4], const uint32_t b[2]) {
    asm volatile(
        "mma.sync.aligned.m16n8k8.row.col.f32.tf32.tf32.f32 "
        "{%0,%1,%2,%3}, {%4,%5,%6,%7}, {%8,%9}, {%0,%1,%2,%3};"
        : "+f"(c[0]), "+f"(c[1]), "+f"(c[2]), "+f"(c[3])
        : "r"(a[0]), "r"(a[1]), "r"(a[2]), "r"(a[3]), "r"(b[0]), "r"(b[1]));
}

__device__ __forceinline__ void cp16(uint32_t smem_addr, const float* gptr, bool valid) {
    asm volatile(
        "{\n\t.reg .pred p;\n\t"
        "setp.ne.b32 p, %2, 0;\n\t"
        "@p cp.async.cg.shared.global [%0], [%1], 16;\n\t"
        "@!p cp.async.cg.shared.global [%0], [%1], 16, 0;\n\t}"
        :: "r"(smem_addr), "l"(gptr), "r"((int)valid));
}

#define A_ST 20
#define B_ST 136
#define A_SZ (128 * A_ST)
#define B_SZ (16 * B_ST)

template <int EPI, bool DUAL>
__launch_bounds__(256)
__global__ void tf32gemm_kernel(const float* __restrict__ A, const float* __restrict__ B,
                                const float* __restrict__ bias, const float* __restrict__ res,
                                const float* __restrict__ wnorm, float* __restrict__ C,
                                int M, int N, int K,
                                const float* __restrict__ B2, const float* __restrict__ bias2,
                                float* __restrict__ C2) {
    __shared__ uint32_t As[2][A_SZ];
    __shared__ uint32_t Bs[2][B_SZ];
    __shared__ float red2[128][2];

    if (DUAL && blockIdx.y == 1) { B = B2; bias = bias2; C = C2; }
    int colBase = DUAL ? 0 : blockIdx.y * 128;
    int rowBase = blockIdx.x * 128;

    int tid = threadIdx.x;
    int wid = tid >> 5, lane = tid & 31;
    int g = lane >> 2, tg = lane & 3;
    int wr = (wid & 3) * 32;
    int wc = (wid >> 2) * 64;

    float acc[2][8][4];
#pragma unroll
    for (int mt = 0; mt < 2; mt++)
#pragma unroll
        for (int nt = 0; nt < 8; nt++)
#pragma unroll
            for (int q = 0; q < 4; q++) acc[mt][nt][q] = 0.f;

    int ar = tid >> 1, ak = (tid & 1) * 8;
    int bk = tid >> 4, bc = (tid & 15) * 8;
    bool aval = (rowBase + ar) < M;
    const float* aptr = A + (size_t)(rowBase + ar) * K + ak;
    const float* bptr = B + (size_t)bk * N + colBase + bc;

    uint32_t aBase = (uint32_t)__cvta_generic_to_shared(&As[0][0]) + (ar * A_ST + ak) * 4;
    uint32_t bBase = (uint32_t)__cvta_generic_to_shared(&Bs[0][0]) + (bk * B_ST + bc) * 4;

    auto issue = [&](int chunk, int buf) {
        int k0 = chunk * 16;
        uint32_t da = aBase + buf * (A_SZ * 4);
        cp16(da,      aptr + k0,     aval);
        cp16(da + 16, aptr + k0 + 4, aval);
        uint32_t db = bBase + buf * (B_SZ * 4);
        cp16(db,      bptr + (size_t)k0 * N,     true);
        cp16(db + 16, bptr + (size_t)k0 * N + 4, true);
        asm volatile("cp.async.commit_group;");
    };

    auto compute = [&](int buf) {
#pragma unroll
        for (int kk = 0; kk < 16; kk += 8) {
            uint32_t afr[2][4];
#pragma unroll
            for (int mt = 0; mt < 2; mt++) {
                int r = wr + mt * 16 + g;
                afr[mt][0] = As[buf][r * A_ST + kk + tg] + 0x1000u;
                afr[mt][1] = As[buf][(r + 8) * A_ST + kk + tg] + 0x1000u;
                afr[mt][2] = As[buf][r * A_ST + kk + tg + 4] + 0x1000u;
                afr[mt][3] = As[buf][(r + 8) * A_ST + kk + tg + 4] + 0x1000u;
            }
            uint32_t bfr[8][2];
#pragma unroll
            for (int nt = 0; nt < 8; nt++) {
                int cc = wc + nt * 8 + g;
                bfr[nt][0] = Bs[buf][(kk + tg) * B_ST + cc] + 0x1000u;
                bfr[nt][1] = Bs[buf][(kk + tg + 4) * B_ST + cc] + 0x1000u;
            }
#pragma unroll
            for (int mt = 0; mt < 2; mt++)
#pragma unroll
                for (int nt = 0; nt < 8; nt++)
                    mma_tf32(acc[mt][nt], afr[mt], bfr[nt]);
        }
    };

    int nch = K >> 4;
    issue(0, 0);
    for (int i = 0; i < nch; ++i) {
        if (i + 1 < nch) {
            issue(i + 1, (i + 1) & 1);
            asm volatile("cp.async.wait_group 1;");
        } else {
            asm volatile("cp.async.wait_group 0;");
        }
        __syncthreads();
        compute(i & 1);
        __syncthreads();
    }

    if (EPI == 0 || EPI == 1) {
#pragma unroll
        for (int mt = 0; mt < 2; mt++) {
            int r0 = rowBase + wr + mt * 16 + g;
            int r1 = r0 + 8;
#pragma unroll
            for (int nt = 0; nt < 8; nt++) {
                int col = colBase + wc + nt * 8 + tg * 2;
                float bi0 = bias[col], bi1 = bias[col + 1];
                float v00 = acc[mt][nt][0] + bi0, v01 = acc[mt][nt][1] + bi1;
                float v10 = acc[mt][nt][2] + bi0, v11 = acc[mt][nt][3] + bi1;
                if (EPI == 1) {
                    v00 = 0.5f * v00 * (1.f + erff(v00 * 0.70710678118654752f));
                    v01 = 0.5f * v01 * (1.f + erff(v01 * 0.70710678118654752f));
                    v10 = 0.5f * v10 * (1.f + erff(v10 * 0.70710678118654752f));
                    v11 = 0.5f * v11 * (1.f + erff(v11 * 0.70710678118654752f));
                }
                if (r0 < M) *(float2*)(C + (size_t)r0 * N + col) = make_float2(v00, v01);
                if (r1 < M) *(float2*)(C + (size_t)r1 * N + col) = make_float2(v10, v11);
            }
        }
    } else {
        float ssq[2][2] = {{0.f, 0.f}, {0.f, 0.f}};
#pragma unroll
        for (int mt = 0; mt < 2; mt++) {
            int r0 = rowBase + wr + mt * 16 + g;
            int r1 = r0 + 8;
#pragma unroll
            for (int nt = 0; nt < 8; nt++) {
                int col = wc + nt * 8 + tg * 2;
                float bi0 = bias[col], bi1 = bias[col + 1];
                float2 re0 = (r0 < M) ? *(const float2*)(res + (size_t)r0 * 128 + col)
                                      : make_float2(0.f, 0.f);
                float2 re1 = (r1 < M) ? *(const float2*)(res + (size_t)r1 * 128 + col)
                                      : make_float2(0.f, 0.f);
                float v00 = acc[mt][nt][0] + bi0 + re0.x, v01 = acc[mt][nt][1] + bi1 + re0.y;
                float v10 = acc[mt][nt][2] + bi0 + re1.x, v11 = acc[mt][nt][3] + bi1 + re1.y;
                acc[mt][nt][0] = v00; acc[mt][nt][1] = v01;
                acc[mt][nt][2] = v10; acc[mt][nt][3] = v11;
                ssq[mt][0] += v00 * v00 + v01 * v01;
                ssq[mt][1] += v10 * v10 + v11 * v11;
            }
        }
#pragma unroll
        for (int mt = 0; mt < 2; mt++)
#pragma unroll
            for (int o = 1; o < 4; o <<= 1) {
                ssq[mt][0] += __shfl_xor_sync(0xffffffffu, ssq[mt][0], o);
                ssq[mt][1] += __shfl_xor_sync(0xffffffffu, ssq[mt][1], o);
            }
        int half = wid >> 2;
        if (tg == 0) {
#pragma unroll
            for (int mt = 0; mt < 2; mt++) {
                red2[wr + mt * 16 + g][half]     = ssq[mt][0];
                red2[wr + mt * 16 + g + 8][half] = ssq[mt][1];
            }
        }
        __syncthreads();
#pragma unroll
        for (int mt = 0; mt < 2; mt++) {
            int lr0 = wr + mt * 16 + g, lr1 = lr0 + 8;
            float sc0 = rsqrtf((red2[lr0][0] + red2[lr0][1]) * (1.f / 128.f) + RMS_EPS);
            float sc1 = rsqrtf((red2[lr1][0] + red2[lr1][1]) * (1.f / 128.f) + RMS_EPS);
            int r0 = rowBase + lr0, r1 = rowBase + lr1;
#pragma unroll
            for (int nt = 0; nt < 8; nt++) {
                int col = wc + nt * 8 + tg * 2;
                float w0 = wnorm[col], w1 = wnorm[col + 1];
                if (r0 < M) *(float2*)(C + (size_t)r0 * 128 + col) =
                    make_float2(acc[mt][nt][0] * sc0 * w0, acc[mt][nt][1] * sc0 * w1);
                if (r1 < M) *(float2*)(C + (size_t)r1 * 128 + col) =
                    make_float2(acc[mt][nt][2] * sc1 * w0, acc[mt][nt][3] * sc1 * w1);
            }
        }
    }
}

// ============================ CSR build =====================================
__global__ void hist_kernel(const int* __restrict__ ei, int E) {
    int e = blockIdx.x * blockDim.x + threadIdx.x;
    if (e < E) atomicAdd(&g_deg[ei[E + e]], 1);
}

__global__ void scan1_kernel(int n) {
    __shared__ int wsum[32];
    int t = threadIdx.x, lane = t & 31, w = t >> 5;
    int idx = blockIdx.x * 1024 + t;
    int v = (idx < n) ? g_deg[idx] : 0;
    int s = v;
#pragma unroll
    for (int o = 1; o < 32; o <<= 1) {
        int u = __shfl_up_sync(0xffffffffu, s, o);
        if (lane >= o) s += u;
    }
    if (lane == 31) wsum[w] = s;
    __syncthreads();
    if (w == 0) {
        int xv = wsum[lane];
#pragma unroll
        for (int o = 1; o < 32; o <<= 1) {
            int u = __shfl_up_sync(0xffffffffu, xv, o);
            if (lane >= o) xv += u;
        }
        wsum[lane] = xv;
    }
    __syncthreads();
    int incl = s + (w ? wsum[w - 1] : 0);
    if (idx < n) g_rowptr[idx] = incl;
    if (t == 1023) g_bsum[blockIdx.x] = incl;
}

__global__ void scan3_kernel(int n, int nb, int Etot) {
    __shared__ int sboff[64];
    int t = threadIdx.x;
    if (t < 32) {
        int v0 = (t < nb)      ? g_bsum[t]      : 0;
        int v1 = (t + 32 < nb) ? g_bsum[t + 32] : 0;
        int s0 = v0;
#pragma unroll
        for (int o = 1; o < 32; o <<= 1) {
            int u = __shfl_up_sync(0xffffffffu, s0, o);
            if (t >= o) s0 += u;
        }
        int tot0 = __shfl_sync(0xffffffffu, s0, 31);
        int s1 = v1;
#pragma unroll
        for (int o = 1; o < 32; o <<= 1) {
            int u = __shfl_up_sync(0xffffffffu, s1, o);
            if (t >= o) s1 += u;
        }
        s1 += tot0;
        sboff[t]      = s0 - v0;
        sboff[t + 32] = s1 - v1;
    }
    __syncthreads();
    int idx = blockIdx.x * 1024 + t;
    if (idx < n) {
        int excl = g_rowptr[idx] - g_deg[idx] + sboff[blockIdx.x];
        g_rowptr[idx] = excl;
        g_cursor[idx] = excl;
    }
    if (blockIdx.x == 0 && t == 0) g_rowptr[n] = Etot;
}

// ============= scatter (src, edge_id) into CSR order ========================
__global__ void scatter_kernel(const int* __restrict__ ei, int E) {
    int e = blockIdx.x * blockDim.x + threadIdx.x;
    if (e >= E) return;
    int dst = ei[E + e];
    int pos = atomicAdd(&g_cursor[dst], 1);
    g_pse[pos] = make_int2(ei[e], e);
}

// ===== fused: per-edge logits + online softmax aggregate + residual + norm ==
__global__ void gather_fused_kernel(const float* __restrict__ x,
                                    const float* __restrict__ ea,
                                    const float* __restrict__ We,
                                    const float* __restrict__ att,
                                    const float* __restrict__ bias_gat,
                                    const float* __restrict__ wn1,
                                    const float* __restrict__ xl,
                                    const float* __restrict__ xr, int N) {
    __shared__ __half2 sWe2[16][64];   // (We[k][2j], We[k][2j+1])
    __shared__ float4  sAtt4[32];
    for (int i = threadIdx.x; i < 1024; i += blockDim.x) {
        int k = i >> 6, j = i & 63;
        sWe2[k][j] = __floats2half2_rn(We[k * 128 + 2 * j], We[k * 128 + 2 * j + 1]);
    }
    if (threadIdx.x < 32) sAtt4[threadIdx.x] = ((const float4*)att)[threadIdx.x];
    __syncthreads();

    int lane = threadIdx.x & 31;
    int n = blockIdx.x * (blockDim.x >> 5) + (threadIdx.x >> 5);
    if (n >= N) return;
    int beg = g_rowptr[n], end = g_rowptr[n + 1];

    int j0 = lane * 2;
    float4 attv = sAtt4[lane];
    float4 xrv = *(const float4*)(xr + (size_t)n * 128 + lane * 4);

    float4 acc = make_float4(0.f, 0.f, 0.f, 0.f);
    float den = 0.f, mx = -INFINITY;

    for (int j = beg; j < end; j++) {
        int2 se = g_pse[j];
        int src = se.x;

        // ea -> half2(dup) bits, broadcast
        float a = (lane < 16) ? ea[(size_t)se.y * 16 + lane] : 0.f;
        __half2 hd = __float2half2_rn(a);
        uint32_t ub = *reinterpret_cast<uint32_t*>(&hd);
        uint32_t avh[16];
#pragma unroll
        for (int k = 0; k < 16; k++) avh[k] = __shfl_sync(0xffffffffu, ub, k);

        __half2 ev01 = __floats2half2_rn(0.f, 0.f);
        __half2 ev23 = ev01;
#pragma unroll
        for (int k = 0; k < 16; k++) {
            __half2 av = *reinterpret_cast<__half2*>(&avh[k]);
            ev01 = __hfma2(av, sWe2[k][j0],     ev01);
            ev23 = __hfma2(av, sWe2[k][j0 + 1], ev23);
        }
        float2 e01 = __half22float2(ev01);
        float2 e23 = __half22float2(ev23);

        float4 xlv = *(const float4*)(xl + (size_t)src * 128 + lane * 4);

        float m0 = xlv.x + xrv.x + e01.x;
        float m1 = xlv.y + xrv.y + e01.y;
        float m2 = xlv.z + xrv.z + e23.x;
        float m3 = xlv.w + xrv.w + e23.y;
        float s0 = fmaxf(m0, 0.2f * m0);
        float s1 = fmaxf(m1, 0.2f * m1);
        float s2 = fmaxf(m2, 0.2f * m2);
        float s3 = fmaxf(m3, 0.2f * m3);

        float p = s0 * attv.x;
        p = fmaf(s1, attv.y, p);
        p = fmaf(s2, attv.z, p);
        p = fmaf(s3, attv.w, p);
        // reduce within 8-lane head group -> every lane holds its head's logit
        p += __shfl_xor_sync(0xffffffffu, p, 1);
        p += __shfl_xor_sync(0xffffffffu, p, 2);
        p += __shfl_xor_sync(0xffffffffu, p, 4);

        // online softmax update
        float nm = fmaxf(mx, p);
        float f  = __expf(mx - nm);   // 0 on first edge (exp(-inf))
        float eh = __expf(p - nm);
        acc.x = fmaf(acc.x, f, eh * xlv.x);
        acc.y = fmaf(acc.y, f, eh * xlv.y);
        acc.z = fmaf(acc.z, f, eh * xlv.z);
        acc.w = fmaf(acc.w, f, eh * xlv.w);
        den = fmaf(den, f, eh);
        mx = nm;
    }

    float inv = 1.f / (den + 1e-16f);
    size_t base = (size_t)n * 128 + lane * 4;
    float4 xv = *(const float4*)(x + base);
    float4 bg = ((const float4*)bias_gat)[lane];
    float4 v = make_float4(acc.x * inv + bg.x + xv.x,
                           acc.y * inv + bg.y + xv.y,
                           acc.z * inv + bg.z + xv.z,
                           acc.w * inv + bg.w + xv.w);

    float ssq = v.x * v.x + v.y * v.y + v.z * v.z + v.w * v.w;
#pragma unroll
    for (int off = 16; off; off >>= 1)
        ssq += __shfl_xor_sync(0xffffffffu, ssq, off);
    float scale = rsqrtf(ssq * (1.f / 128.f) + RMS_EPS);

    float4 wv = ((const float4*)wn1)[lane];
    *(float4*)(g_h + base) = make_float4(v.x * scale * wv.x, v.y * scale * wv.y,
                                         v.z * scale * wv.z, v.w * scale * wv.w);
}

// ================================ launch ====================================
extern "C" void kernel_launch(void* const* d_in, const int* in_sizes, int n_in,
                              void* d_out, int out_size) {
    const float* x        = (const float*)d_in[0];
    const int*   ei       = (const int*)  d_in[1];
    const float* ea       = (const float*)d_in[2];
    const float* Wl       = (const float*)d_in[3];
    const float* bl       = (const float*)d_in[4];
    const float* Wr       = (const float*)d_in[5];
    const float* br       = (const float*)d_in[6];
    const float* We       = (const float*)d_in[7];
    const float* att      = (const float*)d_in[8];
    const float* bias_gat = (const float*)d_in[9];
    const float* wn1      = (const float*)d_in[10];
    const float* wn2      = (const float*)d_in[11];
    const float* w1       = (const float*)d_in[12];
    const float* b1       = (const float*)d_in[13];
    const float* w2       = (const float*)d_in[14];
    const float* b2       = (const float*)d_in[15];

    int N = in_sizes[0] / 128;
    int E = in_sizes[1] / 2;

    void *p_xl, *p_h, *p_H1, *p_deg;
    cudaGetSymbolAddress(&p_xl, g_xl);
    cudaGetSymbolAddress(&p_h, g_h);
    cudaGetSymbolAddress(&p_H1, g_H1);
    cudaGetSymbolAddress(&p_deg, g_deg);

    cudaMemsetAsync(p_deg, 0, (size_t)N * sizeof(int));

    int gx = (N + 127) / 128;
    int nb = (N + 1023) / 1024;
    float* p_xr = (float*)p_H1;   // dead until FFN1 overwrites it

    // xl = x@Wl+bl, xr = x@Wr+br in one dual launch
    tf32gemm_kernel<0, true><<<dim3(gx, 2), 256>>>(x, Wl, bl, nullptr, nullptr, (float*)p_xl,
                                                   N, 128, 128, Wr, br, p_xr);

    // CSR build + permutation
    hist_kernel<<<(E + 255) / 256, 256>>>(ei, E);
    scan1_kernel<<<nb, 1024>>>(N);
    scan3_kernel<<<nb, 1024>>>(N, nb, E);
    scatter_kernel<<<(E + 255) / 256, 256>>>(ei, E);

    // fused logits + online-softmax aggregation + bias + residual + rmsnorm1
    gather_fused_kernel<<<(N + 7) / 8, 256>>>(x, ea, We, att, bias_gat, wn1,
                                              (const float*)p_xl, p_xr, N);

    // FFN
    tf32gemm_kernel<1, false><<<dim3(gx, 4), 256>>>((const float*)p_h, w1, b1, nullptr, nullptr,
                                                    (float*)p_H1, N, 512, 128,
                                                    nullptr, nullptr, nullptr);
    tf32gemm_kernel<2, false><<<dim3(gx, 1), 256>>>((const float*)p_H1, w2, b2, (const float*)p_h,
                                                    wn2, (float*)d_out, N, 128, 512,
                                                    nullptr, nullptr, nullptr);
}

// round 14
// speedup vs baseline: 1.0048x; 1.0048x over previous
#include <cuda_runtime.h>
#include <cuda_fp16.h>
#include <math.h>
#include <stdint.h>

#define NN 50000
#define EE 800000
#define RMS_EPS 1.1920928955078125e-07f

// ---------------- scratch (static __device__, no runtime alloc) -------------
__device__ float  g_xl[NN * 128];
__device__ float  g_h[NN * 128];        // post-norm1 hidden
__device__ float  g_H1[NN * 512];       // FFN intermediate (head reused as xr)
__device__ int2   g_pse[EE];            // (src, edge_id) in CSR order
__device__ int    g_rowptr[NN + 1];
__device__ int    g_cursor[NN];
__device__ int    g_deg[NN];
__device__ int    g_bsum[64];

// ============================ tf32 tensor-core GEMM =========================
__device__ __forceinline__ void mma_tf32(float c[4], const uint32_t a[4], const uint32_t b[2]) {
    asm volatile(
        "mma.sync.aligned.m16n8k8.row.col.f32.tf32.tf32.f32 "
        "{%0,%1,%2,%3}, {%4,%5,%6,%7}, {%8,%9}, {%0,%1,%2,%3};"
        : "+f"(c[0]), "+f"(c[1]), "+f"(c[2]), "+f"(c[3])
        : "r"(a[0]), "r"(a[1]), "r"(a[2]), "r"(a[3]), "r"(b[0]), "r"(b[1]));
}

__device__ __forceinline__ void cp16(uint32_t smem_addr, const float* gptr, bool valid) {
    asm volatile(
        "{\n\t.reg .pred p;\n\t"
        "setp.ne.b32 p, %2, 0;\n\t"
        "@p cp.async.cg.shared.global [%0], [%1], 16;\n\t"
        "@!p cp.async.cg.shared.global [%0], [%1], 16, 0;\n\t}"
        :: "r"(smem_addr), "l"(gptr), "r"((int)valid));
}

#define A_ST 20
#define B_ST 136
#define A_SZ (128 * A_ST)
#define B_SZ (16 * B_ST)

template <int EPI, bool DUAL>
__launch_bounds__(256)
__global__ void tf32gemm_kernel(const float* __restrict__ A, const float* __restrict__ B,
                                const float* __restrict__ bias, const float* __restrict__ res,
                                const float* __restrict__ wnorm, float* __restrict__ C,
                                int M, int N, int K,
                                const float* __restrict__ B2, const float* __restrict__ bias2,
                                float* __restrict__ C2) {
    __shared__ uint32_t As[2][A_SZ];
    __shared__ uint32_t Bs[2][B_SZ];
    __shared__ float red2[128][2];

    if (DUAL && blockIdx.y == 1) { B = B2; bias = bias2; C = C2; }
    int colBase = DUAL ? 0 : blockIdx.y * 128;
    int rowBase = blockIdx.x * 128;

    int tid = threadIdx.x;
    int wid = tid >> 5, lane = tid & 31;
    int g = lane >> 2, tg = lane & 3;
    int wr = (wid & 3) * 32;
    int wc = (wid >> 2) * 64;

    float acc[2][8][4];
#pragma unroll
    for (int mt = 0; mt < 2; mt++)
#pragma unroll
        for (int nt = 0; nt < 8; nt++)
#pragma unroll
            for (int q = 0; q < 4; q++) acc[mt][nt][q] = 0.f;

    int ar = tid >> 1, ak = (tid & 1) * 8;
    int bk = tid >> 4, bc = (tid & 15) * 8;
    bool aval = (rowBase + ar) < M;
    const float* aptr = A + (size_t)(rowBase + ar) * K + ak;
    const float* bptr = B + (size_t)bk * N + colBase + bc;

    uint32_t aBase = (uint32_t)__cvta_generic_to_shared(&As[0][0]) + (ar * A_ST + ak) * 4;
    uint32_t bBase = (uint32_t)__cvta_generic_to_shared(&Bs[0][0]) + (bk * B_ST + bc) * 4;

    auto issue = [&](int chunk, int buf) {
        int k0 = chunk * 16;
        uint32_t da = aBase + buf * (A_SZ * 4);
        cp16(da,      aptr + k0,     aval);
        cp16(da + 16, aptr + k0 + 4, aval);
        uint32_t db = bBase + buf * (B_SZ * 4);
        cp16(db,      bptr + (size_t)k0 * N,     true);
        cp16(db + 16, bptr + (size_t)k0 * N + 4, true);
        asm volatile("cp.async.commit_group;");
    };

    auto compute = [&](int buf) {
#pragma unroll
        for (int kk = 0; kk < 16; kk += 8) {
            uint32_t afr[2][4];
#pragma unroll
            for (int mt = 0; mt < 2; mt++) {
                int r = wr + mt * 16 + g;
                afr[mt][0] = As[buf][r * A_ST + kk + tg] + 0x1000u;
                afr[mt][1] = As[buf][(r + 8) * A_ST + kk + tg] + 0x1000u;
                afr[mt][2] = As[buf][r * A_ST + kk + tg + 4] + 0x1000u;
                afr[mt][3] = As[buf][(r + 8) * A_ST + kk + tg + 4] + 0x1000u;
            }
            uint32_t bfr[8][2];
#pragma unroll
            for (int nt = 0; nt < 8; nt++) {
                int cc = wc + nt * 8 + g;
                bfr[nt][0] = Bs[buf][(kk + tg) * B_ST + cc] + 0x1000u;
                bfr[nt][1] = Bs[buf][(kk + tg + 4) * B_ST + cc] + 0x1000u;
            }
#pragma unroll
            for (int mt = 0; mt < 2; mt++)
#pragma unroll
                for (int nt = 0; nt < 8; nt++)
                    mma_tf32(acc[mt][nt], afr[mt], bfr[nt]);
        }
    };

    int nch = K >> 4;
    issue(0, 0);
    for (int i = 0; i < nch; ++i) {
        if (i + 1 < nch) {
            issue(i + 1, (i + 1) & 1);
            asm volatile("cp.async.wait_group 1;");
        } else {
            asm volatile("cp.async.wait_group 0;");
        }
        __syncthreads();
        compute(i & 1);
        __syncthreads();
    }

    if (EPI == 0 || EPI == 1) {
#pragma unroll
        for (int mt = 0; mt < 2; mt++) {
            int r0 = rowBase + wr + mt * 16 + g;
            int r1 = r0 + 8;
#pragma unroll
            for (int nt = 0; nt < 8; nt++) {
                int col = colBase + wc + nt * 8 + tg * 2;
                float bi0 = bias[col], bi1 = bias[col + 1];
                float v00 = acc[mt][nt][0] + bi0, v01 = acc[mt][nt][1] + bi1;
                float v10 = acc[mt][nt][2] + bi0, v11 = acc[mt][nt][3] + bi1;
                if (EPI == 1) {
                    v00 = 0.5f * v00 * (1.f + erff(v00 * 0.70710678118654752f));
                    v01 = 0.5f * v01 * (1.f + erff(v01 * 0.70710678118654752f));
                    v10 = 0.5f * v10 * (1.f + erff(v10 * 0.70710678118654752f));
                    v11 = 0.5f * v11 * (1.f + erff(v11 * 0.70710678118654752f));
                }
                if (r0 < M) *(float2*)(C + (size_t)r0 * N + col) = make_float2(v00, v01);
                if (r1 < M) *(float2*)(C + (size_t)r1 * N + col) = make_float2(v10, v11);
            }
        }
    } else {
        float ssq[2][2] = {{0.f, 0.f}, {0.f, 0.f}};
#pragma unroll
        for (int mt = 0; mt < 2; mt++) {
            int r0 = rowBase + wr + mt * 16 + g;
            int r1 = r0 + 8;
#pragma unroll
            for (int nt = 0; nt < 8; nt++) {
                int col = wc + nt * 8 + tg * 2;
                float bi0 = bias[col], bi1 = bias[col + 1];
                float2 re0 = (r0 < M) ? *(const float2*)(res + (size_t)r0 * 128 + col)
                                      : make_float2(0.f, 0.f);
                float2 re1 = (r1 < M) ? *(const float2*)(res + (size_t)r1 * 128 + col)
                                      : make_float2(0.f, 0.f);
                float v00 = acc[mt][nt][0] + bi0 + re0.x, v01 = acc[mt][nt][1] + bi1 + re0.y;
                float v10 = acc[mt][nt][2] + bi0 + re1.x, v11 = acc[mt][nt][3] + bi1 + re1.y;
                acc[mt][nt][0] = v00; acc[mt][nt][1] = v01;
                acc[mt][nt][2] = v10; acc[mt][nt][3] = v11;
                ssq[mt][0] += v00 * v00 + v01 * v01;
                ssq[mt][1] += v10 * v10 + v11 * v11;
            }
        }
#pragma unroll
        for (int mt = 0; mt < 2; mt++)
#pragma unroll
            for (int o = 1; o < 4; o <<= 1) {
                ssq[mt][0] += __shfl_xor_sync(0xffffffffu, ssq[mt][0], o);
                ssq[mt][1] += __shfl_xor_sync(0xffffffffu, ssq[mt][1], o);
            }
        int half = wid >> 2;
        if (tg == 0) {
#pragma unroll
            for (int mt = 0; mt < 2; mt++) {
                red2[wr + mt * 16 + g][half]     = ssq[mt][0];
                red2[wr + mt * 16 + g + 8][half] = ssq[mt][1];
            }
        }
        __syncthreads();
#pragma unroll
        for (int mt = 0; mt < 2; mt++) {
            int lr0 = wr + mt * 16 + g, lr1 = lr0 + 8;
            float sc0 = rsqrtf((red2[lr0][0] + red2[lr0][1]) * (1.f / 128.f) + RMS_EPS);
            float sc1 = rsqrtf((red2[lr1][0] + red2[lr1][1]) * (1.f / 128.f) + RMS_EPS);
            int r0 = rowBase + lr0, r1 = rowBase + lr1;
#pragma unroll
            for (int nt = 0; nt < 8; nt++) {
                int col = wc + nt * 8 + tg * 2;
                float w0 = wnorm[col], w1 = wnorm[col + 1];
                if (r0 < M) *(float2*)(C + (size_t)r0 * 128 + col) =
                    make_float2(acc[mt][nt][0] * sc0 * w0, acc[mt][nt][1] * sc0 * w1);
                if (r1 < M) *(float2*)(C + (size_t)r1 * 128 + col) =
                    make_float2(acc[mt][nt][2] * sc1 * w0, acc[mt][nt][3] * sc1 * w1);
            }
        }
    }
}

// ============================ CSR build =====================================
__global__ void hist_kernel(const int* __restrict__ ei, int E) {
    int e = blockIdx.x * blockDim.x + threadIdx.x;
    if (e < E) atomicAdd(&g_deg[ei[E + e]], 1);
}

__global__ void scan1_kernel(int n) {
    __shared__ int wsum[32];
    int t = threadIdx.x, lane = t & 31, w = t >> 5;
    int idx = blockIdx.x * 1024 + t;
    int v = (idx < n) ? g_deg[idx] : 0;
    int s = v;
#pragma unroll
    for (int o = 1; o < 32; o <<= 1) {
        int u = __shfl_up_sync(0xffffffffu, s, o);
        if (lane >= o) s += u;
    }
    if (lane == 31) wsum[w] = s;
    __syncthreads();
    if (w == 0) {
        int xv = wsum[lane];
#pragma unroll
        for (int o = 1; o < 32; o <<= 1) {
            int u = __shfl_up_sync(0xffffffffu, xv, o);
            if (lane >= o) xv += u;
        }
        wsum[lane] = xv;
    }
    __syncthreads();
    int incl = s + (w ? wsum[w - 1] : 0);
    if (idx < n) g_rowptr[idx] = incl;
    if (t == 1023) g_bsum[blockIdx.x] = incl;
}

__global__ void scan3_kernel(int n, int nb, int Etot) {
    __shared__ int sboff[64];
    int t = threadIdx.x;
    if (t < 32) {
        int v0 = (t < nb)      ? g_bsum[t]      : 0;
        int v1 = (t + 32 < nb) ? g_bsum[t + 32] : 0;
        int s0 = v0;
#pragma unroll
        for (int o = 1; o < 32; o <<= 1) {
            int u = __shfl_up_sync(0xffffffffu, s0, o);
            if (t >= o) s0 += u;
        }
        int tot0 = __shfl_sync(0xffffffffu, s0, 31);
        int s1 = v1;
#pragma unroll
        for (int o = 1; o < 32; o <<= 1) {
            int u = __shfl_up_sync(0xffffffffu, s1, o);
            if (t >= o) s1 += u;
        }
        s1 += tot0;
        sboff[t]      = s0 - v0;
        sboff[t + 32] = s1 - v1;
    }
    __syncthreads();
    int idx = blockIdx.x * 1024 + t;
    if (idx < n) {
        int excl = g_rowptr[idx] - g_deg[idx] + sboff[blockIdx.x];
        g_rowptr[idx] = excl;
        g_cursor[idx] = excl;
    }
    if (blockIdx.x == 0 && t == 0) g_rowptr[n] = Etot;
}

// ============= scatter (src, edge_id) into CSR order ========================
__global__ void scatter_kernel(const int* __restrict__ ei, int E) {
    int e = blockIdx.x * blockDim.x + threadIdx.x;
    if (e >= E) return;
    int dst = ei[E + e];
    int pos = atomicAdd(&g_cursor[dst], 1);
    g_pse[pos] = make_int2(ei[e], e);
}

// ===== fused: per-edge logits + online softmax aggregate + residual + norm ==
__global__ void gather_fused_kernel(const float* __restrict__ x,
                                    const float* __restrict__ ea,
                                    const float* __restrict__ We,
                                    const float* __restrict__ att,
                                    const float* __restrict__ bias_gat,
                                    const float* __restrict__ wn1,
                                    const float* __restrict__ xl,
                                    const float* __restrict__ xr, int N) {
    __shared__ __half2 sWe2[16][64];   // (We[k][2j], We[k][2j+1])
    __shared__ float4  sAtt4[32];
    for (int i = threadIdx.x; i < 1024; i += blockDim.x) {
        int k = i >> 6, j = i & 63;
        sWe2[k][j] = __floats2half2_rn(We[k * 128 + 2 * j], We[k * 128 + 2 * j + 1]);
    }
    if (threadIdx.x < 32) sAtt4[threadIdx.x] = ((const float4*)att)[threadIdx.x];
    __syncthreads();

    int lane = threadIdx.x & 31;
    int n = blockIdx.x * (blockDim.x >> 5) + (threadIdx.x >> 5);
    if (n >= N) return;
    int beg = g_rowptr[n], end = g_rowptr[n + 1];

    int j0 = lane * 2;
    float4 attv = sAtt4[lane];
    float4 xrv = *(const float4*)(xr + (size_t)n * 128 + lane * 4);

    float4 acc = make_float4(0.f, 0.f, 0.f, 0.f);
    float den = 0.f, mx = -INFINITY;

    for (int j = beg; j < end; j++) {
        int2 se = g_pse[j];
        int src = se.x;

        // ea -> half2(dup) bits, broadcast
        float a = (lane < 16) ? ea[(size_t)se.y * 16 + lane] : 0.f;
        __half2 hd = __float2half2_rn(a);
        uint32_t ub = *reinterpret_cast<uint32_t*>(&hd);
        uint32_t avh[16];
#pragma unroll
        for (int k = 0; k < 16; k++) avh[k] = __shfl_sync(0xffffffffu, ub, k);

        __half2 ev01 = __floats2half2_rn(0.f, 0.f);
        __half2 ev23 = ev01;
#pragma unroll
        for (int k = 0; k < 16; k++) {
            __half2 av = *reinterpret_cast<__half2*>(&avh[k]);
            ev01 = __hfma2(av, sWe2[k][j0],     ev01);
            ev23 = __hfma2(av, sWe2[k][j0 + 1], ev23);
        }
        float2 e01 = __half22float2(ev01);
        float2 e23 = __half22float2(ev23);

        float4 xlv = *(const float4*)(xl + (size_t)src * 128 + lane * 4);

        float m0 = xlv.x + xrv.x + e01.x;
        float m1 = xlv.y + xrv.y + e01.y;
        float m2 = xlv.z + xrv.z + e23.x;
        float m3 = xlv.w + xrv.w + e23.y;
        float s0 = fmaxf(m0, 0.2f * m0);
        float s1 = fmaxf(m1, 0.2f * m1);
        float s2 = fmaxf(m2, 0.2f * m2);
        float s3 = fmaxf(m3, 0.2f * m3);

        float p = s0 * attv.x;
        p = fmaf(s1, attv.y, p);
        p = fmaf(s2, attv.z, p);
        p = fmaf(s3, attv.w, p);
        // reduce within 8-lane head group -> every lane holds its head's logit
        p += __shfl_xor_sync(0xffffffffu, p, 1);
        p += __shfl_xor_sync(0xffffffffu, p, 2);
        p += __shfl_xor_sync(0xffffffffu, p, 4);

        // online softmax update
        float nm = fmaxf(mx, p);
        float f  = __expf(mx - nm);   // 0 on first edge (exp(-inf))
        float eh = __expf(p - nm);
        acc.x = fmaf(acc.x, f, eh * xlv.x);
        acc.y = fmaf(acc.y, f, eh * xlv.y);
        acc.z = fmaf(acc.z, f, eh * xlv.z);
        acc.w = fmaf(acc.w, f, eh * xlv.w);
        den = fmaf(den, f, eh);
        mx = nm;
    }

    float inv = 1.f / (den + 1e-16f);
    size_t base = (size_t)n * 128 + lane * 4;
    float4 xv = *(const float4*)(x + base);
    float4 bg = ((const float4*)bias_gat)[lane];
    float4 v = make_float4(acc.x * inv + bg.x + xv.x,
                           acc.y * inv + bg.y + xv.y,
                           acc.z * inv + bg.z + xv.z,
                           acc.w * inv + bg.w + xv.w);

    float ssq = v.x * v.x + v.y * v.y + v.z * v.z + v.w * v.w;
#pragma unroll
    for (int off = 16; off; off >>= 1)
        ssq += __shfl_xor_sync(0xffffffffu, ssq, off);
    float scale = rsqrtf(ssq * (1.f / 128.f) + RMS_EPS);

    float4 wv = ((const float4*)wn1)[lane];
    *(float4*)(g_h + base) = make_float4(v.x * scale * wv.x, v.y * scale * wv.y,
                                         v.z * scale * wv.z, v.w * scale * wv.w);
}

// ================================ launch ====================================
extern "C" void kernel_launch(void* const* d_in, const int* in_sizes, int n_in,
                              void* d_out, int out_size) {
    const float* x        = (const float*)d_in[0];
    const int*   ei       = (const int*)  d_in[1];
    const float* ea       = (const float*)d_in[2];
    const float* Wl       = (const float*)d_in[3];
    const float* bl       = (const float*)d_in[4];
    const float* Wr       = (const float*)d_in[5];
    const float* br       = (const float*)d_in[6];
    const float* We       = (const float*)d_in[7];
    const float* att      = (const float*)d_in[8];
    const float* bias_gat = (const float*)d_in[9];
    const float* wn1      = (const float*)d_in[10];
    const float* wn2      = (const float*)d_in[11];
    const float* w1       = (const float*)d_in[12];
    const float* b1       = (const float*)d_in[13];
    const float* w2       = (const float*)d_in[14];
    const float* b2       = (const float*)d_in[15];

    int N = in_sizes[0] / 128;
    int E = in_sizes[1] / 2;

    void *p_xl, *p_h, *p_H1, *p_deg;
    cudaGetSymbolAddress(&p_xl, g_xl);
    cudaGetSymbolAddress(&p_h, g_h);
    cudaGetSymbolAddress(&p_H1, g_H1);
    cudaGetSymbolAddress(&p_deg, g_deg);

    cudaMemsetAsync(p_deg, 0, (size_t)N * sizeof(int));

    int gx = (N + 127) / 128;
    int nb = (N + 1023) / 1024;
    float* p_xr = (float*)p_H1;   // dead until FFN1 overwrites it

    // xl = x@Wl+bl, xr = x@Wr+br in one dual launch
    tf32gemm_kernel<0, true><<<dim3(gx, 2), 256>>>(x, Wl, bl, nullptr, nullptr, (float*)p_xl,
                                                   N, 128, 128, Wr, br, p_xr);

    // CSR build + permutation
    hist_kernel<<<(E + 255) / 256, 256>>>(ei, E);
    scan1_kernel<<<nb, 1024>>>(N);
    scan3_kernel<<<nb, 1024>>>(N, nb, E);
    scatter_kernel<<<(E + 255) / 256, 256>>>(ei, E);

    // fused logits + online-softmax aggregation + bias + residual + rmsnorm1
    gather_fused_kernel<<<(N + 7) / 8, 256>>>(x, ea, We, att, bias_gat, wn1,
                                              (const float*)p_xl, p_xr, N);

    // FFN
    tf32gemm_kernel<1, false><<<dim3(gx, 4), 256>>>((const float*)p_h, w1, b1, nullptr, nullptr,
                                                    (float*)p_H1, N, 512, 128,
                                                    nullptr, nullptr, nullptr);
    tf32gemm_kernel<2, false><<<dim3(gx, 1), 256>>>((const float*)p_H1, w2, b2, (const float*)p_h,
                                                    wn2, (float*)d_out, N, 128, 512,
                                                    nullptr, nullptr, nullptr);
}

// round 15
// speedup vs baseline: 1.0086x; 1.0038x over previous
#include <cuda_runtime.h>
#include <cuda_fp16.h>
#include <math.h>
#include <stdint.h>

#define NN 50000
#define EE 800000
#define RMS_EPS 1.1920928955078125e-07f

// ---------------- scratch (static __device__, no runtime alloc) -------------
__device__ float  g_xl[NN * 128];
__device__ float  g_h[NN * 128];        // post-norm1 hidden
__device__ float  g_H1[NN * 512];       // FFN intermediate (head reused as xr)
__device__ int2   g_pse[EE];            // (src, edge_id) in CSR order
__device__ int    g_rowptr[NN + 1];
__device__ int    g_cursor[NN];
__device__ int    g_deg[NN];
__device__ int    g_bsum[64];

// ============================ tf32 tensor-core GEMM =========================
__device__ __forceinline__ void mma_tf32(float c[4], const uint32_t a[4], const uint32_t b[2]) {
    asm volatile(
        "mma.sync.aligned.m16n8k8.row.col.f32.tf32.tf32.f32 "
        "{%0,%1,%2,%3}, {%4,%5,%6,%7}, {%8,%9}, {%0,%1,%2,%3};"
        : "+f"(c[0]), "+f"(c[1]), "+f"(c[2]), "+f"(c[3])
        : "r"(a[0]), "r"(a[1]), "r"(a[2]), "r"(a[3]), "r"(b[0]), "r"(b[1]));
}

__device__ __forceinline__ void cp16(uint32_t smem_addr, const float* gptr, bool valid) {
    asm volatile(
        "{\n\t.reg .pred p;\n\t"
        "setp.ne.b32 p, %2, 0;\n\t"
        "@p cp.async.cg.shared.global [%0], [%1], 16;\n\t"
        "@!p cp.async.cg.shared.global [%0], [%1], 16, 0;\n\t}"
        :: "r"(smem_addr), "l"(gptr), "r"((int)valid));
}

#define A_ST 20
#define B_ST 136
#define A_SZ (128 * A_ST)
#define B_SZ (16 * B_ST)

template <int EPI, bool DUAL>
__launch_bounds__(256)
__global__ void tf32gemm_kernel(const float* __restrict__ A, const float* __restrict__ B,
                                const float* __restrict__ bias, const float* __restrict__ res,
                                const float* __restrict__ wnorm, float* __restrict__ C,
                                int M, int N, int K,
                                const float* __restrict__ B2, const float* __restrict__ bias2,
                                float* __restrict__ C2) {
    __shared__ uint32_t As[2][A_SZ];
    __shared__ uint32_t Bs[2][B_SZ];
    __shared__ float red2[128][2];

    if (DUAL && blockIdx.y == 1) { B = B2; bias = bias2; C = C2; }
    int colBase = DUAL ? 0 : blockIdx.y * 128;
    int rowBase = blockIdx.x * 128;

    int tid = threadIdx.x;
    int wid = tid >> 5, lane = tid & 31;
    int g = lane >> 2, tg = lane & 3;
    int wr = (wid & 3) * 32;
    int wc = (wid >> 2) * 64;

    float acc[2][8][4];
#pragma unroll
    for (int mt = 0; mt < 2; mt++)
#pragma unroll
        for (int nt = 0; nt < 8; nt++)
#pragma unroll
            for (int q = 0; q < 4; q++) acc[mt][nt][q] = 0.f;

    int ar = tid >> 1, ak = (tid & 1) * 8;
    int bk = tid >> 4, bc = (tid & 15) * 8;
    bool aval = (rowBase + ar) < M;
    const float* aptr = A + (size_t)(rowBase + ar) * K + ak;
    const float* bptr = B + (size_t)bk * N + colBase + bc;

    uint32_t aBase = (uint32_t)__cvta_generic_to_shared(&As[0][0]) + (ar * A_ST + ak) * 4;
    uint32_t bBase = (uint32_t)__cvta_generic_to_shared(&Bs[0][0]) + (bk * B_ST + bc) * 4;

    auto issue = [&](int chunk, int buf) {
        int k0 = chunk * 16;
        uint32_t da = aBase + buf * (A_SZ * 4);
        cp16(da,      aptr + k0,     aval);
        cp16(da + 16, aptr + k0 + 4, aval);
        uint32_t db = bBase + buf * (B_SZ * 4);
        cp16(db,      bptr + (size_t)k0 * N,     true);
        cp16(db + 16, bptr + (size_t)k0 * N + 4, true);
        asm volatile("cp.async.commit_group;");
    };

    auto compute = [&](int buf) {
#pragma unroll
        for (int kk = 0; kk < 16; kk += 8) {
            uint32_t afr[2][4];
#pragma unroll
            for (int mt = 0; mt < 2; mt++) {
                int r = wr + mt * 16 + g;
                afr[mt][0] = As[buf][r * A_ST + kk + tg] + 0x1000u;
                afr[mt][1] = As[buf][(r + 8) * A_ST + kk + tg] + 0x1000u;
                afr[mt][2] = As[buf][r * A_ST + kk + tg + 4] + 0x1000u;
                afr[mt][3] = As[buf][(r + 8) * A_ST + kk + tg + 4] + 0x1000u;
            }
            uint32_t bfr[8][2];
#pragma unroll
            for (int nt = 0; nt < 8; nt++) {
                int cc = wc + nt * 8 + g;
                bfr[nt][0] = Bs[buf][(kk + tg) * B_ST + cc] + 0x1000u;
                bfr[nt][1] = Bs[buf][(kk + tg + 4) * B_ST + cc] + 0x1000u;
            }
#pragma unroll
            for (int mt = 0; mt < 2; mt++)
#pragma unroll
                for (int nt = 0; nt < 8; nt++)
                    mma_tf32(acc[mt][nt], afr[mt], bfr[nt]);
        }
    };

    int nch = K >> 4;
    issue(0, 0);
    for (int i = 0; i < nch; ++i) {
        if (i + 1 < nch) {
            issue(i + 1, (i + 1) & 1);
            asm volatile("cp.async.wait_group 1;");
        } else {
            asm volatile("cp.async.wait_group 0;");
        }
        __syncthreads();
        compute(i & 1);
        __syncthreads();
    }

    if (EPI == 0 || EPI == 1) {
#pragma unroll
        for (int mt = 0; mt < 2; mt++) {
            int r0 = rowBase + wr + mt * 16 + g;
            int r1 = r0 + 8;
#pragma unroll
            for (int nt = 0; nt < 8; nt++) {
                int col = colBase + wc + nt * 8 + tg * 2;
                float bi0 = bias[col], bi1 = bias[col + 1];
                float v00 = acc[mt][nt][0] + bi0, v01 = acc[mt][nt][1] + bi1;
                float v10 = acc[mt][nt][2] + bi0, v11 = acc[mt][nt][3] + bi1;
                if (EPI == 1) {
                    v00 = 0.5f * v00 * (1.f + erff(v00 * 0.70710678118654752f));
                    v01 = 0.5f * v01 * (1.f + erff(v01 * 0.70710678118654752f));
                    v10 = 0.5f * v10 * (1.f + erff(v10 * 0.70710678118654752f));
                    v11 = 0.5f * v11 * (1.f + erff(v11 * 0.70710678118654752f));
                }
                if (r0 < M) *(float2*)(C + (size_t)r0 * N + col) = make_float2(v00, v01);
                if (r1 < M) *(float2*)(C + (size_t)r1 * N + col) = make_float2(v10, v11);
            }
        }
    } else {
        float ssq[2][2] = {{0.f, 0.f}, {0.f, 0.f}};
#pragma unroll
        for (int mt = 0; mt < 2; mt++) {
            int r0 = rowBase + wr + mt * 16 + g;
            int r1 = r0 + 8;
#pragma unroll
            for (int nt = 0; nt < 8; nt++) {
                int col = wc + nt * 8 + tg * 2;
                float bi0 = bias[col], bi1 = bias[col + 1];
                float2 re0 = (r0 < M) ? *(const float2*)(res + (size_t)r0 * 128 + col)
                                      : make_float2(0.f, 0.f);
                float2 re1 = (r1 < M) ? *(const float2*)(res + (size_t)r1 * 128 + col)
                                      : make_float2(0.f, 0.f);
                float v00 = acc[mt][nt][0] + bi0 + re0.x, v01 = acc[mt][nt][1] + bi1 + re0.y;
                float v10 = acc[mt][nt][2] + bi0 + re1.x, v11 = acc[mt][nt][3] + bi1 + re1.y;
                acc[mt][nt][0] = v00; acc[mt][nt][1] = v01;
                acc[mt][nt][2] = v10; acc[mt][nt][3] = v11;
                ssq[mt][0] += v00 * v00 + v01 * v01;
                ssq[mt][1] += v10 * v10 + v11 * v11;
            }
        }
#pragma unroll
        for (int mt = 0; mt < 2; mt++)
#pragma unroll
            for (int o = 1; o < 4; o <<= 1) {
                ssq[mt][0] += __shfl_xor_sync(0xffffffffu, ssq[mt][0], o);
                ssq[mt][1] += __shfl_xor_sync(0xffffffffu, ssq[mt][1], o);
            }
        int half = wid >> 2;
        if (tg == 0) {
#pragma unroll
            for (int mt = 0; mt < 2; mt++) {
                red2[wr + mt * 16 + g][half]     = ssq[mt][0];
                red2[wr + mt * 16 + g + 8][half] = ssq[mt][1];
            }
        }
        __syncthreads();
#pragma unroll
        for (int mt = 0; mt < 2; mt++) {
            int lr0 = wr + mt * 16 + g, lr1 = lr0 + 8;
            float sc0 = rsqrtf((red2[lr0][0] + red2[lr0][1]) * (1.f / 128.f) + RMS_EPS);
            float sc1 = rsqrtf((red2[lr1][0] + red2[lr1][1]) * (1.f / 128.f) + RMS_EPS);
            int r0 = rowBase + lr0, r1 = rowBase + lr1;
#pragma unroll
            for (int nt = 0; nt < 8; nt++) {
                int col = wc + nt * 8 + tg * 2;
                float w0 = wnorm[col], w1 = wnorm[col + 1];
                if (r0 < M) *(float2*)(C + (size_t)r0 * 128 + col) =
                    make_float2(acc[mt][nt][0] * sc0 * w0, acc[mt][nt][1] * sc0 * w1);
                if (r1 < M) *(float2*)(C + (size_t)r1 * 128 + col) =
                    make_float2(acc[mt][nt][2] * sc1 * w0, acc[mt][nt][3] * sc1 * w1);
            }
        }
    }
}

// ============================ CSR build =====================================
__global__ void hist_kernel(const int* __restrict__ ei, int E) {
    int e = blockIdx.x * blockDim.x + threadIdx.x;
    if (e < E) atomicAdd(&g_deg[ei[E + e]], 1);
}

__global__ void scan1_kernel(int n) {
    __shared__ int wsum[32];
    int t = threadIdx.x, lane = t & 31, w = t >> 5;
    int idx = blockIdx.x * 1024 + t;
    int v = (idx < n) ? g_deg[idx] : 0;
    int s = v;
#pragma unroll
    for (int o = 1; o < 32; o <<= 1) {
        int u = __shfl_up_sync(0xffffffffu, s, o);
        if (lane >= o) s += u;
    }
    if (lane == 31) wsum[w] = s;
    __syncthreads();
    if (w == 0) {
        int xv = wsum[lane];
#pragma unroll
        for (int o = 1; o < 32; o <<= 1) {
            int u = __shfl_up_sync(0xffffffffu, xv, o);
            if (lane >= o) xv += u;
        }
        wsum[lane] = xv;
    }
    __syncthreads();
    int incl = s + (w ? wsum[w - 1] : 0);
    if (idx < n) g_rowptr[idx] = incl;
    if (t == 1023) g_bsum[blockIdx.x] = incl;
}

__global__ void scan3_kernel(int n, int nb, int Etot) {
    __shared__ int sboff[64];
    int t = threadIdx.x;
    if (t < 32) {
        int v0 = (t < nb)      ? g_bsum[t]      : 0;
        int v1 = (t + 32 < nb) ? g_bsum[t + 32] : 0;
        int s0 = v0;
#pragma unroll
        for (int o = 1; o < 32; o <<= 1) {
            int u = __shfl_up_sync(0xffffffffu, s0, o);
            if (t >= o) s0 += u;
        }
        int tot0 = __shfl_sync(0xffffffffu, s0, 31);
        int s1 = v1;
#pragma unroll
        for (int o = 1; o < 32; o <<= 1) {
            int u = __shfl_up_sync(0xffffffffu, s1, o);
            if (t >= o) s1 += u;
        }
        s1 += tot0;
        sboff[t]      = s0 - v0;
        sboff[t + 32] = s1 - v1;
    }
    __syncthreads();
    int idx = blockIdx.x * 1024 + t;
    if (idx < n) {
        int excl = g_rowptr[idx] - g_deg[idx] + sboff[blockIdx.x];
        g_rowptr[idx] = excl;
        g_cursor[idx] = excl;
    }
    if (blockIdx.x == 0 && t == 0) g_rowptr[n] = Etot;
}

// ============= scatter (src, edge_id) into CSR order ========================
__global__ void scatter_kernel(const int* __restrict__ ei, int E) {
    int e = blockIdx.x * blockDim.x + threadIdx.x;
    if (e >= E) return;
    int dst = ei[E + e];
    int pos = atomicAdd(&g_cursor[dst], 1);
    g_pse[pos] = make_int2(ei[e], e);
}

// ===== fused: per-edge logits + online softmax aggregate + residual + norm ==
__global__ void gather_fused_kernel(const float* __restrict__ x,
                                    const float* __restrict__ ea,
                                    const float* __restrict__ We,
                                    const float* __restrict__ att,
                                    const float* __restrict__ bias_gat,
                                    const float* __restrict__ wn1,
                                    const float* __restrict__ xl,
                                    const float* __restrict__ xr, int N) {
    __shared__ __half2 sWe2[16][64];   // (We[k][2j], We[k][2j+1])
    __shared__ float4  sAtt4[32];
    for (int i = threadIdx.x; i < 1024; i += blockDim.x) {
        int k = i >> 6, j = i & 63;
        sWe2[k][j] = __floats2half2_rn(We[k * 128 + 2 * j], We[k * 128 + 2 * j + 1]);
    }
    if (threadIdx.x < 32) sAtt4[threadIdx.x] = ((const float4*)att)[threadIdx.x];
    __syncthreads();

    int lane = threadIdx.x & 31;
    int n = blockIdx.x * (blockDim.x >> 5) + (threadIdx.x >> 5);
    if (n >= N) return;
    int beg = g_rowptr[n], end = g_rowptr[n + 1];

    int j0 = lane * 2;
    float4 attv = sAtt4[lane];
    float4 xrv = *(const float4*)(xr + (size_t)n * 128 + lane * 4);

    float4 acc = make_float4(0.f, 0.f, 0.f, 0.f);
    float den = 0.f, mx = -INFINITY;

    for (int j = beg; j < end; j++) {
        int2 se = g_pse[j];
        int src = se.x;

        // ea -> half2(dup) bits, broadcast
        float a = (lane < 16) ? ea[(size_t)se.y * 16 + lane] : 0.f;
        __half2 hd = __float2half2_rn(a);
        uint32_t ub = *reinterpret_cast<uint32_t*>(&hd);
        uint32_t avh[16];
#pragma unroll
        for (int k = 0; k < 16; k++) avh[k] = __shfl_sync(0xffffffffu, ub, k);

        __half2 ev01 = __floats2half2_rn(0.f, 0.f);
        __half2 ev23 = ev01;
#pragma unroll
        for (int k = 0; k < 16; k++) {
            __half2 av = *reinterpret_cast<__half2*>(&avh[k]);
            ev01 = __hfma2(av, sWe2[k][j0],     ev01);
            ev23 = __hfma2(av, sWe2[k][j0 + 1], ev23);
        }
        float2 e01 = __half22float2(ev01);
        float2 e23 = __half22float2(ev23);

        float4 xlv = *(const float4*)(xl + (size_t)src * 128 + lane * 4);

        float m0 = xlv.x + xrv.x + e01.x;
        float m1 = xlv.y + xrv.y + e01.y;
        float m2 = xlv.z + xrv.z + e23.x;
        float m3 = xlv.w + xrv.w + e23.y;
        float s0 = fmaxf(m0, 0.2f * m0);
        float s1 = fmaxf(m1, 0.2f * m1);
        float s2 = fmaxf(m2, 0.2f * m2);
        float s3 = fmaxf(m3, 0.2f * m3);

        float p = s0 * attv.x;
        p = fmaf(s1, attv.y, p);
        p = fmaf(s2, attv.z, p);
        p = fmaf(s3, attv.w, p);
        // reduce within 8-lane head group -> every lane holds its head's logit
        p += __shfl_xor_sync(0xffffffffu, p, 1);
        p += __shfl_xor_sync(0xffffffffu, p, 2);
        p += __shfl_xor_sync(0xffffffffu, p, 4);

        // online softmax update
        float nm = fmaxf(mx, p);
        float f  = __expf(mx - nm);   // 0 on first edge (exp(-inf))
        float eh = __expf(p - nm);
        acc.x = fmaf(acc.x, f, eh * xlv.x);
        acc.y = fmaf(acc.y, f, eh * xlv.y);
        acc.z = fmaf(acc.z, f, eh * xlv.z);
        acc.w = fmaf(acc.w, f, eh * xlv.w);
        den = fmaf(den, f, eh);
        mx = nm;
    }

    float inv = 1.f / (den + 1e-16f);
    size_t base = (size_t)n * 128 + lane * 4;
    float4 xv = *(const float4*)(x + base);
    float4 bg = ((const float4*)bias_gat)[lane];
    float4 v = make_float4(acc.x * inv + bg.x + xv.x,
                           acc.y * inv + bg.y + xv.y,
                           acc.z * inv + bg.z + xv.z,
                           acc.w * inv + bg.w + xv.w);

    float ssq = v.x * v.x + v.y * v.y + v.z * v.z + v.w * v.w;
#pragma unroll
    for (int off = 16; off; off >>= 1)
        ssq += __shfl_xor_sync(0xffffffffu, ssq, off);
    float scale = rsqrtf(ssq * (1.f / 128.f) + RMS_EPS);

    float4 wv = ((const float4*)wn1)[lane];
    *(float4*)(g_h + base) = make_float4(v.x * scale * wv.x, v.y * scale * wv.y,
                                         v.z * scale * wv.z, v.w * scale * wv.w);
}

// ================================ launch ====================================
extern "C" void kernel_launch(void* const* d_in, const int* in_sizes, int n_in,
                              void* d_out, int out_size) {
    const float* x        = (const float*)d_in[0];
    const int*   ei       = (const int*)  d_in[1];
    const float* ea       = (const float*)d_in[2];
    const float* Wl       = (const float*)d_in[3];
    const float* bl       = (const float*)d_in[4];
    const float* Wr       = (const float*)d_in[5];
    const float* br       = (const float*)d_in[6];
    const float* We       = (const float*)d_in[7];
    const float* att      = (const float*)d_in[8];
    const float* bias_gat = (const float*)d_in[9];
    const float* wn1      = (const float*)d_in[10];
    const float* wn2      = (const float*)d_in[11];
    const float* w1       = (const float*)d_in[12];
    const float* b1       = (const float*)d_in[13];
    const float* w2       = (const float*)d_in[14];
    const float* b2       = (const float*)d_in[15];

    int N = in_sizes[0] / 128;
    int E = in_sizes[1] / 2;

    void *p_xl, *p_h, *p_H1, *p_deg;
    cudaGetSymbolAddress(&p_xl, g_xl);
    cudaGetSymbolAddress(&p_h, g_h);
    cudaGetSymbolAddress(&p_H1, g_H1);
    cudaGetSymbolAddress(&p_deg, g_deg);

    cudaMemsetAsync(p_deg, 0, (size_t)N * sizeof(int));

    int gx = (N + 127) / 128;
    int nb = (N + 1023) / 1024;
    float* p_xr = (float*)p_H1;   // dead until FFN1 overwrites it

    // xl = x@Wl+bl, xr = x@Wr+br in one dual launch
    tf32gemm_kernel<0, true><<<dim3(gx, 2), 256>>>(x, Wl, bl, nullptr, nullptr, (float*)p_xl,
                                                   N, 128, 128, Wr, br, p_xr);

    // CSR build + permutation
    hist_kernel<<<(E + 255) / 256, 256>>>(ei, E);
    scan1_kernel<<<nb, 1024>>>(N);
    scan3_kernel<<<nb, 1024>>>(N, nb, E);
    scatter_kernel<<<(E + 255) / 256, 256>>>(ei, E);

    // fused logits + online-softmax aggregation + bias + residual + rmsnorm1
    gather_fused_kernel<<<(N + 7) / 8, 256>>>(x, ea, We, att, bias_gat, wn1,
                                              (const float*)p_xl, p_xr, N);

    // FFN
    tf32gemm_kernel<1, false><<<dim3(gx, 4), 256>>>((const float*)p_h, w1, b1, nullptr, nullptr,
                                                    (float*)p_H1, N, 512, 128,
                                                    nullptr, nullptr, nullptr);
    tf32gemm_kernel<2, false><<<dim3(gx, 1), 256>>>((const float*)p_H1, w2, b2, (const float*)p_h,
                                                    wn2, (float*)d_out, N, 128, 512,
                                                    nullptr, nullptr, nullptr);
}

// round 16
// speedup vs baseline: 1.0121x; 1.0035x over previous
#include <cuda_runtime.h>
#include <cuda_fp16.h>
#include <math.h>
#include <stdint.h>

#define NN 50000
#define EE 800000
#define RMS_EPS 1.1920928955078125e-07f

// ---------------- scratch (static __device__, no runtime alloc) -------------
__device__ float  g_xl[NN * 128];
__device__ float  g_h[NN * 128];        // post-norm1 hidden
__device__ float  g_H1[NN * 512];       // FFN intermediate (head reused as xr)
__device__ int2   g_pse[EE];            // (src, edge_id) in CSR order
__device__ int    g_rowptr[NN + 1];
__device__ int    g_cursor[NN];
__device__ int    g_deg[NN];
__device__ int    g_bsum[64];

// ============================ tf32 tensor-core GEMM =========================
__device__ __forceinline__ void mma_tf32(float c[4], const uint32_t a[4], const uint32_t b[2]) {
    asm volatile(
        "mma.sync.aligned.m16n8k8.row.col.f32.tf32.tf32.f32 "
        "{%0,%1,%2,%3}, {%4,%5,%6,%7}, {%8,%9}, {%0,%1,%2,%3};"
        : "+f"(c[0]), "+f"(c[1]), "+f"(c[2]), "+f"(c[3])
        : "r"(a[0]), "r"(a[1]), "r"(a[2]), "r"(a[3]), "r"(b[0]), "r"(b[1]));
}

__device__ __forceinline__ void cp16(uint32_t smem_addr, const float* gptr, bool valid) {
    asm volatile(
        "{\n\t.reg .pred p;\n\t"
        "setp.ne.b32 p, %2, 0;\n\t"
        "@p cp.async.cg.shared.global [%0], [%1], 16;\n\t"
        "@!p cp.async.cg.shared.global [%0], [%1], 16, 0;\n\t}"
        :: "r"(smem_addr), "l"(gptr), "r"((int)valid));
}

#define A_ST 20
#define B_ST 136
#define A_SZ (128 * A_ST)
#define B_SZ (16 * B_ST)

template <int EPI, bool DUAL>
__launch_bounds__(256)
__global__ void tf32gemm_kernel(const float* __restrict__ A, const float* __restrict__ B,
                                const float* __restrict__ bias, const float* __restrict__ res,
                                const float* __restrict__ wnorm, float* __restrict__ C,
                                int M, int N, int K,
                                const float* __restrict__ B2, const float* __restrict__ bias2,
                                float* __restrict__ C2) {
    __shared__ uint32_t As[2][A_SZ];
    __shared__ uint32_t Bs[2][B_SZ];
    __shared__ float red2[128][2];

    if (DUAL && blockIdx.y == 1) { B = B2; bias = bias2; C = C2; }
    int colBase = DUAL ? 0 : blockIdx.y * 128;
    int rowBase = blockIdx.x * 128;

    int tid = threadIdx.x;
    int wid = tid >> 5, lane = tid & 31;
    int g = lane >> 2, tg = lane & 3;
    int wr = (wid & 3) * 32;
    int wc = (wid >> 2) * 64;

    float acc[2][8][4];
#pragma unroll
    for (int mt = 0; mt < 2; mt++)
#pragma unroll
        for (int nt = 0; nt < 8; nt++)
#pragma unroll
            for (int q = 0; q < 4; q++) acc[mt][nt][q] = 0.f;

    int ar = tid >> 1, ak = (tid & 1) * 8;
    int bk = tid >> 4, bc = (tid & 15) * 8;
    bool aval = (rowBase + ar) < M;
    const float* aptr = A + (size_t)(rowBase + ar) * K + ak;
    const float* bptr = B + (size_t)bk * N + colBase + bc;

    uint32_t aBase = (uint32_t)__cvta_generic_to_shared(&As[0][0]) + (ar * A_ST + ak) * 4;
    uint32_t bBase = (uint32_t)__cvta_generic_to_shared(&Bs[0][0]) + (bk * B_ST + bc) * 4;

    auto issue = [&](int chunk, int buf) {
        int k0 = chunk * 16;
        uint32_t da = aBase + buf * (A_SZ * 4);
        cp16(da,      aptr + k0,     aval);
        cp16(da + 16, aptr + k0 + 4, aval);
        uint32_t db = bBase + buf * (B_SZ * 4);
        cp16(db,      bptr + (size_t)k0 * N,     true);
        cp16(db + 16, bptr + (size_t)k0 * N + 4, true);
        asm volatile("cp.async.commit_group;");
    };

    auto compute = [&](int buf) {
#pragma unroll
        for (int kk = 0; kk < 16; kk += 8) {
            uint32_t afr[2][4];
#pragma unroll
            for (int mt = 0; mt < 2; mt++) {
                int r = wr + mt * 16 + g;
                afr[mt][0] = As[buf][r * A_ST + kk + tg] + 0x1000u;
                afr[mt][1] = As[buf][(r + 8) * A_ST + kk + tg] + 0x1000u;
                afr[mt][2] = As[buf][r * A_ST + kk + tg + 4] + 0x1000u;
                afr[mt][3] = As[buf][(r + 8) * A_ST + kk + tg + 4] + 0x1000u;
            }
            uint32_t bfr[8][2];
#pragma unroll
            for (int nt = 0; nt < 8; nt++) {
                int cc = wc + nt * 8 + g;
                bfr[nt][0] = Bs[buf][(kk + tg) * B_ST + cc] + 0x1000u;
                bfr[nt][1] = Bs[buf][(kk + tg + 4) * B_ST + cc] + 0x1000u;
            }
#pragma unroll
            for (int mt = 0; mt < 2; mt++)
#pragma unroll
                for (int nt = 0; nt < 8; nt++)
                    mma_tf32(acc[mt][nt], afr[mt], bfr[nt]);
        }
    };

    // single-sync double-buffered mainloop:
    // sync_i orders all warps' compute(i-1) [reader of buf^1] before issue(i+1) [writer of buf^1]
    int nch = K >> 4;
    issue(0, 0);
    int buf = 0;
    for (int i = 0; i < nch; ++i) {
        asm volatile("cp.async.wait_group 0;");
        __syncthreads();
        if (i + 1 < nch) issue(i + 1, buf ^ 1);
        compute(buf);
        buf ^= 1;
    }

    if (EPI == 0 || EPI == 1) {
#pragma unroll
        for (int mt = 0; mt < 2; mt++) {
            int r0 = rowBase + wr + mt * 16 + g;
            int r1 = r0 + 8;
#pragma unroll
            for (int nt = 0; nt < 8; nt++) {
                int col = colBase + wc + nt * 8 + tg * 2;
                float bi0 = bias[col], bi1 = bias[col + 1];
                float v00 = acc[mt][nt][0] + bi0, v01 = acc[mt][nt][1] + bi1;
                float v10 = acc[mt][nt][2] + bi0, v11 = acc[mt][nt][3] + bi1;
                if (EPI == 1) {
                    v00 = 0.5f * v00 * (1.f + erff(v00 * 0.70710678118654752f));
                    v01 = 0.5f * v01 * (1.f + erff(v01 * 0.70710678118654752f));
                    v10 = 0.5f * v10 * (1.f + erff(v10 * 0.70710678118654752f));
                    v11 = 0.5f * v11 * (1.f + erff(v11 * 0.70710678118654752f));
                }
                if (r0 < M) *(float2*)(C + (size_t)r0 * N + col) = make_float2(v00, v01);
                if (r1 < M) *(float2*)(C + (size_t)r1 * N + col) = make_float2(v10, v11);
            }
        }
    } else {
        float ssq[2][2] = {{0.f, 0.f}, {0.f, 0.f}};
#pragma unroll
        for (int mt = 0; mt < 2; mt++) {
            int r0 = rowBase + wr + mt * 16 + g;
            int r1 = r0 + 8;
#pragma unroll
            for (int nt = 0; nt < 8; nt++) {
                int col = wc + nt * 8 + tg * 2;
                float bi0 = bias[col], bi1 = bias[col + 1];
                float2 re0 = (r0 < M) ? *(const float2*)(res + (size_t)r0 * 128 + col)
                                      : make_float2(0.f, 0.f);
                float2 re1 = (r1 < M) ? *(const float2*)(res + (size_t)r1 * 128 + col)
                                      : make_float2(0.f, 0.f);
                float v00 = acc[mt][nt][0] + bi0 + re0.x, v01 = acc[mt][nt][1] + bi1 + re0.y;
                float v10 = acc[mt][nt][2] + bi0 + re1.x, v11 = acc[mt][nt][3] + bi1 + re1.y;
                acc[mt][nt][0] = v00; acc[mt][nt][1] = v01;
                acc[mt][nt][2] = v10; acc[mt][nt][3] = v11;
                ssq[mt][0] += v00 * v00 + v01 * v01;
                ssq[mt][1] += v10 * v10 + v11 * v11;
            }
        }
#pragma unroll
        for (int mt = 0; mt < 2; mt++)
#pragma unroll
            for (int o = 1; o < 4; o <<= 1) {
                ssq[mt][0] += __shfl_xor_sync(0xffffffffu, ssq[mt][0], o);
                ssq[mt][1] += __shfl_xor_sync(0xffffffffu, ssq[mt][1], o);
            }
        int half = wid >> 2;
        if (tg == 0) {
#pragma unroll
            for (int mt = 0; mt < 2; mt++) {
                red2[wr + mt * 16 + g][half]     = ssq[mt][0];
                red2[wr + mt * 16 + g + 8][half] = ssq[mt][1];
            }
        }
        __syncthreads();
#pragma unroll
        for (int mt = 0; mt < 2; mt++) {
            int lr0 = wr + mt * 16 + g, lr1 = lr0 + 8;
            float sc0 = rsqrtf((red2[lr0][0] + red2[lr0][1]) * (1.f / 128.f) + RMS_EPS);
            float sc1 = rsqrtf((red2[lr1][0] + red2[lr1][1]) * (1.f / 128.f) + RMS_EPS);
            int r0 = rowBase + lr0, r1 = rowBase + lr1;
#pragma unroll
            for (int nt = 0; nt < 8; nt++) {
                int col = wc + nt * 8 + tg * 2;
                float w0 = wnorm[col], w1 = wnorm[col + 1];
                if (r0 < M) *(float2*)(C + (size_t)r0 * 128 + col) =
                    make_float2(acc[mt][nt][0] * sc0 * w0, acc[mt][nt][1] * sc0 * w1);
                if (r1 < M) *(float2*)(C + (size_t)r1 * 128 + col) =
                    make_float2(acc[mt][nt][2] * sc1 * w0, acc[mt][nt][3] * sc1 * w1);
            }
        }
    }
}

// ============================ CSR build =====================================
__global__ void hist_kernel(const int* __restrict__ ei, int E) {
    int e = blockIdx.x * blockDim.x + threadIdx.x;
    if (e < E) atomicAdd(&g_deg[ei[E + e]], 1);
}

__global__ void scan1_kernel(int n) {
    __shared__ int wsum[32];
    int t = threadIdx.x, lane = t & 31, w = t >> 5;
    int idx = blockIdx.x * 1024 + t;
    int v = (idx < n) ? g_deg[idx] : 0;
    int s = v;
#pragma unroll
    for (int o = 1; o < 32; o <<= 1) {
        int u = __shfl_up_sync(0xffffffffu, s, o);
        if (lane >= o) s += u;
    }
    if (lane == 31) wsum[w] = s;
    __syncthreads();
    if (w == 0) {
        int xv = wsum[lane];
#pragma unroll
        for (int o = 1; o < 32; o <<= 1) {
            int u = __shfl_up_sync(0xffffffffu, xv, o);
            if (lane >= o) xv += u;
        }
        wsum[lane] = xv;
    }
    __syncthreads();
    int incl = s + (w ? wsum[w - 1] : 0);
    if (idx < n) g_rowptr[idx] = incl;
    if (t == 1023) g_bsum[blockIdx.x] = incl;
}

__global__ void scan3_kernel(int n, int nb, int Etot) {
    __shared__ int sboff[64];
    int t = threadIdx.x;
    if (t < 32) {
        int v0 = (t < nb)      ? g_bsum[t]      : 0;
        int v1 = (t + 32 < nb) ? g_bsum[t + 32] : 0;
        int s0 = v0;
#pragma unroll
        for (int o = 1; o < 32; o <<= 1) {
            int u = __shfl_up_sync(0xffffffffu, s0, o);
            if (t >= o) s0 += u;
        }
        int tot0 = __shfl_sync(0xffffffffu, s0, 31);
        int s1 = v1;
#pragma unroll
        for (int o = 1; o < 32; o <<= 1) {
            int u = __shfl_up_sync(0xffffffffu, s1, o);
            if (t >= o) s1 += u;
        }
        s1 += tot0;
        sboff[t]      = s0 - v0;
        sboff[t + 32] = s1 - v1;
    }
    __syncthreads();
    int idx = blockIdx.x * 1024 + t;
    if (idx < n) {
        int excl = g_rowptr[idx] - g_deg[idx] + sboff[blockIdx.x];
        g_rowptr[idx] = excl;
        g_cursor[idx] = excl;
    }
    if (blockIdx.x == 0 && t == 0) g_rowptr[n] = Etot;
}

// ============= scatter (src, edge_id) into CSR order ========================
__global__ void scatter_kernel(const int* __restrict__ ei, int E) {
    int e = blockIdx.x * blockDim.x + threadIdx.x;
    if (e >= E) return;
    int dst = ei[E + e];
    int pos = atomicAdd(&g_cursor[dst], 1);
    g_pse[pos] = make_int2(ei[e], e);
}

// ===== fused: per-edge logits + online softmax aggregate + residual + norm ==
__global__ void gather_fused_kernel(const float* __restrict__ x,
                                    const float* __restrict__ ea,
                                    const float* __restrict__ We,
                                    const float* __restrict__ att,
                                    const float* __restrict__ bias_gat,
                                    const float* __restrict__ wn1,
                                    const float* __restrict__ xl,
                                    const float* __restrict__ xr, int N) {
    __shared__ __half2 sWe2[16][64];   // (We[k][2j], We[k][2j+1])
    __shared__ float4  sAtt4[32];
    for (int i = threadIdx.x; i < 1024; i += blockDim.x) {
        int k = i >> 6, j = i & 63;
        sWe2[k][j] = __floats2half2_rn(We[k * 128 + 2 * j], We[k * 128 + 2 * j + 1]);
    }
    if (threadIdx.x < 32) sAtt4[threadIdx.x] = ((const float4*)att)[threadIdx.x];
    __syncthreads();

    int lane = threadIdx.x & 31;
    int n = blockIdx.x * (blockDim.x >> 5) + (threadIdx.x >> 5);
    if (n >= N) return;
    int beg = g_rowptr[n], end = g_rowptr[n + 1];

    int j0 = lane * 2;
    float4 attv = sAtt4[lane];
    float4 xrv = *(const float4*)(xr + (size_t)n * 128 + lane * 4);

    float4 acc = make_float4(0.f, 0.f, 0.f, 0.f);
    float den = 0.f, mx = -INFINITY;

    for (int j = beg; j < end; j++) {
        int2 se = g_pse[j];
        int src = se.x;

        float a = (lane < 16) ? ea[(size_t)se.y * 16 + lane] : 0.f;
        __half2 hd = __float2half2_rn(a);
        uint32_t ub = *reinterpret_cast<uint32_t*>(&hd);
        uint32_t avh[16];
#pragma unroll
        for (int k = 0; k < 16; k++) avh[k] = __shfl_sync(0xffffffffu, ub, k);

        __half2 ev01 = __floats2half2_rn(0.f, 0.f);
        __half2 ev23 = ev01;
#pragma unroll
        for (int k = 0; k < 16; k++) {
            __half2 av = *reinterpret_cast<__half2*>(&avh[k]);
            ev01 = __hfma2(av, sWe2[k][j0],     ev01);
            ev23 = __hfma2(av, sWe2[k][j0 + 1], ev23);
        }
        float2 e01 = __half22float2(ev01);
        float2 e23 = __half22float2(ev23);

        float4 xlv = *(const float4*)(xl + (size_t)src * 128 + lane * 4);

        float m0 = xlv.x + xrv.x + e01.x;
        float m1 = xlv.y + xrv.y + e01.y;
        float m2 = xlv.z + xrv.z + e23.x;
        float m3 = xlv.w + xrv.w + e23.y;
        float s0 = fmaxf(m0, 0.2f * m0);
        float s1 = fmaxf(m1, 0.2f * m1);
        float s2 = fmaxf(m2, 0.2f * m2);
        float s3 = fmaxf(m3, 0.2f * m3);

        float p = s0 * attv.x;
        p = fmaf(s1, attv.y, p);
        p = fmaf(s2, attv.z, p);
        p = fmaf(s3, attv.w, p);
        p += __shfl_xor_sync(0xffffffffu, p, 1);
        p += __shfl_xor_sync(0xffffffffu, p, 2);
        p += __shfl_xor_sync(0xffffffffu, p, 4);

        float nm = fmaxf(mx, p);
        float f  = __expf(mx - nm);
        float eh = __expf(p - nm);
        acc.x = fmaf(acc.x, f, eh * xlv.x);
        acc.y = fmaf(acc.y, f, eh * xlv.y);
        acc.z = fmaf(acc.z, f, eh * xlv.z);
        acc.w = fmaf(acc.w, f, eh * xlv.w);
        den = fmaf(den, f, eh);
        mx = nm;
    }

    float inv = 1.f / (den + 1e-16f);
    size_t base = (size_t)n * 128 + lane * 4;
    float4 xv = *(const float4*)(x + base);
    float4 bg = ((const float4*)bias_gat)[lane];
    float4 v = make_float4(acc.x * inv + bg.x + xv.x,
                           acc.y * inv + bg.y + xv.y,
                           acc.z * inv + bg.z + xv.z,
                           acc.w * inv + bg.w + xv.w);

    float ssq = v.x * v.x + v.y * v.y + v.z * v.z + v.w * v.w;
#pragma unroll
    for (int off = 16; off; off >>= 1)
        ssq += __shfl_xor_sync(0xffffffffu, ssq, off);
    float scale = rsqrtf(ssq * (1.f / 128.f) + RMS_EPS);

    float4 wv = ((const float4*)wn1)[lane];
    *(float4*)(g_h + base) = make_float4(v.x * scale * wv.x, v.y * scale * wv.y,
                                         v.z * scale * wv.z, v.w * scale * wv.w);
}

// ================================ launch ====================================
extern "C" void kernel_launch(void* const* d_in, const int* in_sizes, int n_in,
                              void* d_out, int out_size) {
    const float* x        = (const float*)d_in[0];
    const int*   ei       = (const int*)  d_in[1];
    const float* ea       = (const float*)d_in[2];
    const float* Wl       = (const float*)d_in[3];
    const float* bl       = (const float*)d_in[4];
    const float* Wr       = (const float*)d_in[5];
    const float* br       = (const float*)d_in[6];
    const float* We       = (const float*)d_in[7];
    const float* att      = (const float*)d_in[8];
    const float* bias_gat = (const float*)d_in[9];
    const float* wn1      = (const float*)d_in[10];
    const float* wn2      = (const float*)d_in[11];
    const float* w1       = (const float*)d_in[12];
    const float* b1       = (const float*)d_in[13];
    const float* w2       = (const float*)d_in[14];
    const float* b2       = (const float*)d_in[15];

    int N = in_sizes[0] / 128;
    int E = in_sizes[1] / 2;

    void *p_xl, *p_h, *p_H1, *p_deg;
    cudaGetSymbolAddress(&p_xl, g_xl);
    cudaGetSymbolAddress(&p_h, g_h);
    cudaGetSymbolAddress(&p_H1, g_H1);
    cudaGetSymbolAddress(&p_deg, g_deg);

    // one-time host-side stream/event handles (no device memory involved)
    static cudaStream_t s2 = nullptr;
    static cudaEvent_t evFork = nullptr, evJoin = nullptr;
    if (s2 == nullptr) {
        cudaStreamCreateWithFlags(&s2, cudaStreamNonBlocking);
        cudaEventCreateWithFlags(&evFork, cudaEventDisableTiming);
        cudaEventCreateWithFlags(&evJoin, cudaEventDisableTiming);
    }

    int gx = (N + 127) / 128;
    int nb = (N + 1023) / 1024;
    float* p_xr = (float*)p_H1;   // dead until FFN1 overwrites it

    // ---- fork: CSR chain on s2, concurrent with the dual GEMM on stream 0 ----
    cudaEventRecord(evFork, 0);
    cudaStreamWaitEvent(s2, evFork, 0);

    cudaMemsetAsync(p_deg, 0, (size_t)N * sizeof(int), s2);
    hist_kernel<<<(E + 255) / 256, 256, 0, s2>>>(ei, E);
    scan1_kernel<<<nb, 1024, 0, s2>>>(N);
    scan3_kernel<<<nb, 1024, 0, s2>>>(N, nb, E);
    scatter_kernel<<<(E + 255) / 256, 256, 0, s2>>>(ei, E);
    cudaEventRecord(evJoin, s2);

    // xl = x@Wl+bl, xr = x@Wr+br in one dual launch (stream 0)
    tf32gemm_kernel<0, true><<<dim3(gx, 2), 256>>>(x, Wl, bl, nullptr, nullptr, (float*)p_xl,
                                                   N, 128, 128, Wr, br, p_xr);

    // ---- join: gather needs both GEMM outputs and the CSR permutation ----
    cudaStreamWaitEvent(0, evJoin, 0);

    gather_fused_kernel<<<(N + 7) / 8, 256>>>(x, ea, We, att, bias_gat, wn1,
                                              (const float*)p_xl, p_xr, N);

    // FFN
    tf32gemm_kernel<1, false><<<dim3(gx, 4), 256>>>((const float*)p_h, w1, b1, nullptr, nullptr,
                                                    (float*)p_H1, N, 512, 128,
                                                    nullptr, nullptr, nullptr);
    tf32gemm_kernel<2, false><<<dim3(gx, 1), 256>>>((const float*)p_H1, w2, b2, (const float*)p_h,
                                                    wn2, (float*)d_out, N, 128, 512,
                                                    nullptr, nullptr, nullptr);
}